// round 13
// baseline (speedup 1.0000x reference)
#include <cuda_runtime.h>
#include <cuda_fp16.h>
#include <math.h>

#define N_NODES 50000
#define N_EDGES 800000
#define HDIM 128
#define CDIM 16

// ---------------- scratch (device globals; no allocation) ----------------
__device__ int   g_is64;
__device__ int   g_cnt[N_NODES];                 // degree; consumed by fill
__device__ int   g_ptr[N_NODES + 1];
__device__ int   g_bsum[64];
__device__ int   g_bflag[64];
__device__ float g_dinv[N_NODES];
__device__ int2  g_edge[N_EDGES];                // CSR: (src, wn-as-bits)
__device__ __half2 g_Whf[4 * 8192 + 1024];       // fp16 "big": W1,W2,W3,lw1,lw2
__device__ __half2 g_Wlf[4 * 8192 + 1024];       // fp16 residuals
__device__ __half2 g_y[(size_t)N_NODES * 64];    // message buffer A
__device__ __half2 g_y2[(size_t)N_NODES * 64];   // message buffer B
__device__ __half2 g_h[(size_t)N_NODES * 64];    // activations (fp16)

// ---------------- init: counters + dtype detect + weight packs + x->fp16 ---
__global__ void k_init(const int* __restrict__ e,
                       const float* __restrict__ W1, const float* __restrict__ W2,
                       const float* __restrict__ W3, const float* __restrict__ lw1,
                       const float* __restrict__ lw2,
                       const float* __restrict__ x, const float* __restrict__ imp) {
    int idx = blockIdx.x * 256 + threadIdx.x;
    if (idx < N_NODES) g_cnt[idx] = 0;
    if (idx < 64) g_bflag[idx] = 0;

    if (idx < 32768) {                           // 4 mats x 8192 (k2,n) half2 packs
        int m = idx >> 13, r = idx & 8191;
        int k2 = r >> 7, n = r & 127;
        const float* src = (m == 0) ? W1 : (m == 1) ? W2 : (m == 2) ? W3 : lw1;
        float w0 = src[(2 * k2) * 128 + n];
        float w1 = src[(2 * k2 + 1) * 128 + n];
        __half h0 = __float2half_rn(w0), h1 = __float2half_rn(w1);
        g_Whf[idx] = __halves2half2(h0, h1);
        g_Wlf[idx] = __halves2half2(__float2half_rn(w0 - __half2float(h0)),
                                    __float2half_rn(w1 - __half2float(h1)));
    } else if (idx < 33792) {                    // lw2: 1024 (k2,n) packs
        int j = idx - 32768;
        int k2 = j >> 4, n = j & 15;
        float w0 = lw2[(2 * k2) * 16 + n];
        float w1 = lw2[(2 * k2 + 1) * 16 + n];
        __half h0 = __float2half_rn(w0), h1 = __float2half_rn(w1);
        g_Whf[32768 + j] = __halves2half2(h0, h1);
        g_Wlf[32768 + j] = __halves2half2(__float2half_rn(w0 - __half2float(h0)),
                                          __float2half_rn(w1 - __half2float(h1)));
    }

    // x * importance -> fp16 into g_h
    for (int j = idx; j < N_NODES * 16; j += 65536) {
        int row = j >> 4, seg = j & 15;
        const float4* px = (const float4*)(x + (size_t)row * HDIM + seg * 8);
        float4 a = px[0], b = px[1];
        const float4* pi = (const float4*)(imp + seg * 8);
        float4 i0 = pi[0], i1 = pi[1];
        __half2 h0 = __floats2half2_rn(a.x * i0.x, a.y * i0.y);
        __half2 h1 = __floats2half2_rn(a.z * i0.z, a.w * i0.w);
        __half2 h2 = __floats2half2_rn(b.x * i1.x, b.y * i1.y);
        __half2 h3 = __floats2half2_rn(b.z * i1.z, b.w * i1.w);
        uint4 o;
        o.x = *(unsigned*)&h0; o.y = *(unsigned*)&h1;
        o.z = *(unsigned*)&h2; o.w = *(unsigned*)&h3;
        *(uint4*)(g_h + (size_t)row * 64 + seg * 4) = o;
    }

    if (blockIdx.x == 0) {
        __shared__ int any;
        if (threadIdx.x == 0) any = 0;
        __syncthreads();
        int w = e[2 * threadIdx.x + 1];   // odd words zero <=> int64 indices
        if (w != 0) atomicOr(&any, 1);
        __syncthreads();
        if (threadIdx.x == 0) g_is64 = (any == 0) ? 1 : 0;
    }
}

// histogram only (no rc store; fill re-reads the L2-hot edge tensor)
__global__ void k_hist(const void* __restrict__ edge) {
    int e = blockIdx.x * blockDim.x + threadIdx.x;
    if (e >= N_EDGES) return;
    int c;
    if (g_is64) c = (int)((const long long*)edge)[N_EDGES + e];
    else        c = ((const int*)edge)[N_EDGES + e];
    atomicAdd(&g_cnt[c], 1);
}

// single-pass exclusive scan with decoupled lookback (+ dinv fused)
__global__ void k_scan() {
    __shared__ int s[1024];
    __shared__ int pre;
    int idx = blockIdx.x * 1024 + threadIdx.x;
    int v = (idx < N_NODES) ? g_cnt[idx] : 0;
    if (idx < N_NODES) g_dinv[idx] = rsqrtf((float)(v + 1));
    s[threadIdx.x] = v;
    __syncthreads();
    for (int off = 1; off < 1024; off <<= 1) {
        int t = (threadIdx.x >= off) ? s[threadIdx.x - off] : 0;
        __syncthreads();
        s[threadIdx.x] += t;
        __syncthreads();
    }
    if (threadIdx.x == 1023) {
        g_bsum[blockIdx.x] = s[1023];
        __threadfence();
        atomicExch(&g_bflag[blockIdx.x], 1);
    }
    if (threadIdx.x < 32) {
        int p = 0;
        for (int i = threadIdx.x; i < blockIdx.x; i += 32) {
            while (atomicAdd(&g_bflag[i], 0) == 0) { __nanosleep(100); }
            p += atomicAdd(&g_bsum[i], 0);
        }
#pragma unroll
        for (int o = 16; o; o >>= 1) p += __shfl_xor_sync(0xffffffffu, p, o);
        if (threadIdx.x == 0) pre = p;
    }
    __syncthreads();
    if (idx < N_NODES) g_ptr[idx] = s[threadIdx.x] - v + pre;
    if (idx == 0) g_ptr[N_NODES] = N_EDGES;
}

// ---------------- mma / math helpers ---------------------------------------
__device__ __forceinline__ void mma_f16(float* d, const unsigned* a, const unsigned* b) {
    asm volatile(
        "mma.sync.aligned.m16n8k16.row.col.f32.f16.f16.f32 "
        "{%0,%1,%2,%3}, {%4,%5,%6,%7}, {%8,%9}, {%0,%1,%2,%3};"
        : "+f"(d[0]), "+f"(d[1]), "+f"(d[2]), "+f"(d[3])
        : "r"(a[0]), "r"(a[1]), "r"(a[2]), "r"(a[3]), "r"(b[0]), "r"(b[1]));
}

__device__ __forceinline__ float gelu_exact(float v) {
    return 0.5f * v * (1.f + erff(v * 0.70710678118654752f));
}

__device__ __forceinline__ void fma8(float* acc, uint4 u, float w) {
    float2 a = __half22float2(*(__half2*)&u.x);
    float2 b = __half22float2(*(__half2*)&u.y);
    float2 c = __half22float2(*(__half2*)&u.z);
    float2 d = __half22float2(*(__half2*)&u.w);
    acc[0] += w * a.x; acc[1] += w * a.y;
    acc[2] += w * b.x; acc[3] += w * b.y;
    acc[4] += w * c.x; acc[5] += w * c.y;
    acc[6] += w * d.x; acc[7] += w * d.y;
}

// ---------------- fused kernel ----------------------------------------------
// MODE 0: grid-strided CSR fill pre-phase, then GEMM (A = g_h from init)
// MODE 1: agg(Yin,+bias,gelu) -> g_h rows of this block, then GEMM -> Yout
// MODE 2: agg phase, then GEMM + fused head projection -> out
#define AHS 20     // half2 stride of A smem row
#define WHS 136    // half2 stride of W smem k-row
#define TSS 68     // half2 stride of fused-final T tile row
#define W2S 20     // half2 stride of lw2 smem k2-row

template <int MODE>
__global__ void k_fused(const void* __restrict__ edge,
                        const __half2* __restrict__ Yin, const float* __restrict__ bias,
                        const __half2* __restrict__ Wh_, const __half2* __restrict__ Wl_,
                        __half2* __restrict__ Yout,
                        const float* __restrict__ lb1,
                        const __half2* __restrict__ W2h_, const __half2* __restrict__ W2l_,
                        const float* __restrict__ lb2, float* __restrict__ out) {
    extern __shared__ unsigned char smraw[];
    __half2* As  = (__half2*)smraw;                    // 128*AHS  (10240 B)
    __half2* Whs = (__half2*)(smraw + 10240);          // 16*WHS   (8704 B)
    __half2* Wls = (__half2*)(smraw + 18944);          // 16*WHS   (8704 B)

    int tid = threadIdx.x, lane = tid & 31, wid = tid >> 5;
    int row0 = blockIdx.x * 128;

    if (MODE == 0) {
        // ---- CSR bucket fill, grid-strided (independent of the GEMM) ----
        const int per = (N_EDGES + gridDim.x - 1) / gridDim.x;
        int base = blockIdx.x * per;
        int lim = min(base + per, N_EDGES);
        if (g_is64) {
            const long long* p = (const long long*)edge;
            for (int e = base + tid; e < lim; e += 256) {
                int r = (int)p[e], c = (int)p[N_EDGES + e];
                int pos = atomicSub(&g_cnt[c], 1) - 1;
                g_edge[g_ptr[c] + pos] = make_int2(r, __float_as_int(g_dinv[r] * g_dinv[c]));
            }
        } else {
            const int* p = (const int*)edge;
            for (int e = base + tid; e < lim; e += 256) {
                int r = p[e], c = p[N_EDGES + e];
                int pos = atomicSub(&g_cnt[c], 1) - 1;
                g_edge[g_ptr[c] + pos] = make_int2(r, __float_as_int(g_dinv[r] * g_dinv[c]));
            }
        }
        // no sync needed: GEMM phase doesn't consume fill results
    }

    if (MODE >= 1) {
        // ---- aggregation phase: this block's 128 nodes -> g_h rows ----
        int grp = tid >> 4, sub = tid & 15;
#pragma unroll 1
        for (int it = 0; it < 8; it++) {
            int c = row0 + it * 16 + grp;
            if (c < N_NODES) {
                float dc = g_dinv[c];
                float acc[8] = {0, 0, 0, 0, 0, 0, 0, 0};
                fma8(acc, *(const uint4*)(Yin + (size_t)c * 64 + sub * 4), dc * dc);
                int beg = g_ptr[c], end = g_ptr[c + 1];
                int i = beg;
                for (; i + 4 <= end; i += 4) {
                    int2 e0 = g_edge[i],     e1 = g_edge[i + 1];
                    int2 e2 = g_edge[i + 2], e3 = g_edge[i + 3];
                    uint4 u0 = *(const uint4*)(Yin + (size_t)e0.x * 64 + sub * 4);
                    uint4 u1 = *(const uint4*)(Yin + (size_t)e1.x * 64 + sub * 4);
                    uint4 u2 = *(const uint4*)(Yin + (size_t)e2.x * 64 + sub * 4);
                    uint4 u3 = *(const uint4*)(Yin + (size_t)e3.x * 64 + sub * 4);
                    fma8(acc, u0, __int_as_float(e0.y));
                    fma8(acc, u1, __int_as_float(e1.y));
                    fma8(acc, u2, __int_as_float(e2.y));
                    fma8(acc, u3, __int_as_float(e3.y));
                }
                for (; i < end; i++) {
                    int2 e = g_edge[i];
                    fma8(acc, *(const uint4*)(Yin + (size_t)e.x * 64 + sub * 4), __int_as_float(e.y));
                }
                const float4 b0 = *(const float4*)(bias + sub * 8);
                const float4 b1 = *(const float4*)(bias + sub * 8 + 4);
                __half2 h0 = __floats2half2_rn(gelu_exact(acc[0] + b0.x), gelu_exact(acc[1] + b0.y));
                __half2 h1 = __floats2half2_rn(gelu_exact(acc[2] + b0.z), gelu_exact(acc[3] + b0.w));
                __half2 h2 = __floats2half2_rn(gelu_exact(acc[4] + b1.x), gelu_exact(acc[5] + b1.y));
                __half2 h3 = __floats2half2_rn(gelu_exact(acc[6] + b1.z), gelu_exact(acc[7] + b1.w));
                uint4 o;
                o.x = *(unsigned*)&h0; o.y = *(unsigned*)&h1;
                o.z = *(unsigned*)&h2; o.w = *(unsigned*)&h3;
                *(uint4*)(g_h + (size_t)c * 64 + sub * 4) = o;
            }
        }
        __syncthreads();   // h rows of this block visible block-wide
    }

    // ---- GEMM phase: A = g_h rows [row0, row0+128) ----
    int wm = wid >> 2, wn = wid & 3;
    int g = lane >> 2, t4 = lane & 3;

    float acc[4][4][4];
#pragma unroll
    for (int mt = 0; mt < 4; mt++)
#pragma unroll
        for (int nt = 0; nt < 4; nt++)
#pragma unroll
            for (int r = 0; r < 4; r++) acc[mt][nt][r] = 0.f;

    int ar = tid >> 1, part = tid & 1;
    int wkr = tid >> 4, wnq = (tid & 15) * 8;

    for (int kt = 0; kt < 4; kt++) {
        uint4 au0 = make_uint4(0, 0, 0, 0), au1 = au0;
        {
            int gr = row0 + ar;
            if (gr < N_NODES) {
                const uint4* p = (const uint4*)(g_h + (size_t)gr * 64 + kt * 16 + part * 8);
                au0 = p[0]; au1 = p[1];
            }
        }
        const uint4* ph = (const uint4*)(Wh_ + (size_t)(kt * 16 + wkr) * 128 + wnq);
        const uint4* pl = (const uint4*)(Wl_ + (size_t)(kt * 16 + wkr) * 128 + wnq);
        uint4 wh0 = ph[0], wh1 = ph[1];
        uint4 wl0 = pl[0], wl1 = pl[1];

        __syncthreads();
        {
            uint4* q = (uint4*)(As + ar * AHS + part * 8);
            q[0] = au0; q[1] = au1;
            uint4* qh = (uint4*)(Whs + wkr * WHS + wnq);
            qh[0] = wh0; qh[1] = wh1;
            uint4* ql = (uint4*)(Wls + wkr * WHS + wnq);
            ql[0] = wl0; ql[1] = wl1;
        }
        __syncthreads();

#pragma unroll
        for (int ks = 0; ks < 2; ks++) {
            int kb = ks * 8;
            unsigned a[4][4];
#pragma unroll
            for (int mt = 0; mt < 4; mt++) {
                int rb = wm * 64 + mt * 16;
                a[mt][0] = *(unsigned*)&As[(rb + g) * AHS + kb + t4];
                a[mt][1] = *(unsigned*)&As[(rb + g + 8) * AHS + kb + t4];
                a[mt][2] = *(unsigned*)&As[(rb + g) * AHS + kb + t4 + 4];
                a[mt][3] = *(unsigned*)&As[(rb + g + 8) * AHS + kb + t4 + 4];
            }
            unsigned bh[4][2], bl[4][2];
#pragma unroll
            for (int nt = 0; nt < 4; nt++) {
                int n0 = wn * 32 + nt * 8;
                bh[nt][0] = *(unsigned*)&Whs[(kb + t4) * WHS + n0 + g];
                bh[nt][1] = *(unsigned*)&Whs[(kb + t4 + 4) * WHS + n0 + g];
                bl[nt][0] = *(unsigned*)&Wls[(kb + t4) * WHS + n0 + g];
                bl[nt][1] = *(unsigned*)&Wls[(kb + t4 + 4) * WHS + n0 + g];
            }
#pragma unroll
            for (int mt = 0; mt < 4; mt++)
#pragma unroll
                for (int nt = 0; nt < 4; nt++) {
                    mma_f16(acc[mt][nt], a[mt], bh[nt]);
                    mma_f16(acc[mt][nt], a[mt], bl[nt]);
                }
        }
    }

    if (MODE <= 1) {
#pragma unroll
        for (int mt = 0; mt < 4; mt++) {
            int r1 = row0 + wm * 64 + mt * 16 + g;
            int r2 = r1 + 8;
#pragma unroll
            for (int nt = 0; nt < 4; nt++) {
                int ch = wn * 16 + nt * 4 + t4;
                if (r1 < N_NODES)
                    Yout[(size_t)r1 * 64 + ch] = __floats2half2_rn(acc[mt][nt][0], acc[mt][nt][1]);
                if (r2 < N_NODES)
                    Yout[(size_t)r2 * 64 + ch] = __floats2half2_rn(acc[mt][nt][2], acc[mt][nt][3]);
            }
        }
    } else {
        // fused head: T = gelu(acc + lb1) in smem, then T @ lw2 (+lb2) -> out
        __half2* Ts   = (__half2*)smraw;                 // 128*TSS  (34816 B)
        __half2* W2hs = (__half2*)(smraw + 34816);       // 64*W2S   (5120 B)
        __half2* W2ls = (__half2*)(smraw + 39936);       // 64*W2S   (5120 B)
        __syncthreads();
        {
            int k2 = tid >> 2, n4 = (tid & 3) * 4;
            *(uint4*)(W2hs + k2 * W2S + n4) = ((const uint4*)W2h_)[tid];
            *(uint4*)(W2ls + k2 * W2S + n4) = ((const uint4*)W2l_)[tid];
        }
#pragma unroll
        for (int mt = 0; mt < 4; mt++) {
            int rl1 = wm * 64 + mt * 16 + g;
            int rl2 = rl1 + 8;
#pragma unroll
            for (int nt = 0; nt < 4; nt++) {
                int c = wn * 32 + nt * 8 + 2 * t4;
                int ch = c >> 1;
                float2 lb = *(const float2*)(lb1 + c);
                Ts[rl1 * TSS + ch] = __floats2half2_rn(gelu_exact(acc[mt][nt][0] + lb.x),
                                                       gelu_exact(acc[mt][nt][1] + lb.y));
                Ts[rl2 * TSS + ch] = __floats2half2_rn(gelu_exact(acc[mt][nt][2] + lb.x),
                                                       gelu_exact(acc[mt][nt][3] + lb.y));
            }
        }
        __syncthreads();
        int rb2 = wid * 16;
        float f2[2][4];
#pragma unroll
        for (int n2 = 0; n2 < 2; n2++)
#pragma unroll
            for (int r = 0; r < 4; r++) f2[n2][r] = 0.f;
#pragma unroll
        for (int kq = 0; kq < 8; kq++) {
            unsigned a[4];
            a[0] = *(unsigned*)&Ts[(rb2 + g) * TSS + kq * 8 + t4];
            a[1] = *(unsigned*)&Ts[(rb2 + g + 8) * TSS + kq * 8 + t4];
            a[2] = *(unsigned*)&Ts[(rb2 + g) * TSS + kq * 8 + t4 + 4];
            a[3] = *(unsigned*)&Ts[(rb2 + g + 8) * TSS + kq * 8 + t4 + 4];
#pragma unroll
            for (int n2 = 0; n2 < 2; n2++) {
                unsigned bh[2], bl[2];
                bh[0] = *(unsigned*)&W2hs[(kq * 8 + t4) * W2S + n2 * 8 + g];
                bh[1] = *(unsigned*)&W2hs[(kq * 8 + t4 + 4) * W2S + n2 * 8 + g];
                bl[0] = *(unsigned*)&W2ls[(kq * 8 + t4) * W2S + n2 * 8 + g];
                bl[1] = *(unsigned*)&W2ls[(kq * 8 + t4 + 4) * W2S + n2 * 8 + g];
                mma_f16(f2[n2], a, bh);
                mma_f16(f2[n2], a, bl);
            }
        }
        int r1 = row0 + rb2 + g, r2 = r1 + 8;
#pragma unroll
        for (int n2 = 0; n2 < 2; n2++) {
            int c = n2 * 8 + 2 * t4;
            float2 lb = *(const float2*)(lb2 + c);
            if (r1 < N_NODES)
                *(float2*)(out + (size_t)r1 * CDIM + c) = make_float2(f2[n2][0] + lb.x, f2[n2][1] + lb.y);
            if (r2 < N_NODES)
                *(float2*)(out + (size_t)r2 * CDIM + c) = make_float2(f2[n2][2] + lb.x, f2[n2][3] + lb.y);
        }
    }
}

// ---------------- launch ---------------------------------------------------
extern "C" void kernel_launch(void* const* d_in, const int* in_sizes, int n_in,
                              void* d_out, int out_size) {
    const float* x    = (const float*)d_in[0];
    const void*  edge = d_in[1];
    const float* imp  = (const float*)d_in[2];
    const float* W1   = (const float*)d_in[3];
    const float* b1   = (const float*)d_in[4];
    const float* W2   = (const float*)d_in[5];
    const float* b2   = (const float*)d_in[6];
    const float* W3   = (const float*)d_in[7];
    const float* b3   = (const float*)d_in[8];
    const float* lw1  = (const float*)d_in[9];
    const float* lb1  = (const float*)d_in[10];
    const float* lw2  = (const float*)d_in[11];
    const float* lb2  = (const float*)d_in[12];
    float* out = (float*)d_out;

    const int EB = (N_EDGES + 255) / 256;      // 3125
    const int SB = (N_NODES + 1023) / 1024;    // 49
    const int GB = (N_NODES + 127) / 128;      // 391

    __half2* ya; cudaGetSymbolAddress((void**)&ya, g_y);
    __half2* yb; cudaGetSymbolAddress((void**)&yb, g_y2);
    __half2* wh; cudaGetSymbolAddress((void**)&wh, g_Whf);
    __half2* wl; cudaGetSymbolAddress((void**)&wl, g_Wlf);

    const int SM_MAIN = 27648;   // As + Wh + Wl
    const int SM_FIN  = 45056;   // Ts + W2h + W2l overlay

    // --- setup: init (counters, packs, x->fp16, dtype), hist, scan ---
    k_init<<<256, 256>>>((const int*)edge, W1, W2, W3, lw1, lw2, x, imp);
    k_hist<<<EB, 256>>>(edge);
    k_scan<<<SB, 1024>>>();

    // --- layer 1: [fill + gemm1] -> ya ---
    k_fused<0><<<GB, 256, SM_MAIN>>>(edge, nullptr, nullptr, wh, wl, ya,
                                     nullptr, nullptr, nullptr, nullptr, nullptr);
    // --- layer 2: [agg(ya,b1) + gemm2] -> yb ---
    k_fused<1><<<GB, 256, SM_MAIN>>>(nullptr, ya, b1, wh + 8192, wl + 8192, yb,
                                     nullptr, nullptr, nullptr, nullptr, nullptr);
    // --- layer 3: [agg(yb,b2) + gemm3] -> ya ---
    k_fused<1><<<GB, 256, SM_MAIN>>>(nullptr, yb, b2, wh + 16384, wl + 16384, ya,
                                     nullptr, nullptr, nullptr, nullptr, nullptr);
    // --- head: [agg(ya,b3) + gemm(lw1) + gelu + @lw2 + lb2] -> out ---
    k_fused<2><<<GB, 256, SM_FIN>>>(nullptr, ya, b3, wh + 24576, wl + 24576, nullptr,
                                    lb1, wh + 32768, wl + 32768, lb2, out);
}

// round 14
// speedup vs baseline: 1.3930x; 1.3930x over previous
#include <cuda_runtime.h>
#include <cuda_fp16.h>
#include <math.h>

#define N_NODES 50000
#define N_EDGES 800000
#define HDIM 128
#define CDIM 16

// ---------------- scratch (device globals; no allocation) ----------------
__device__ int   g_is64;
__device__ int   g_cnt[N_NODES];                 // degree; consumed by fill
__device__ int   g_ptr[N_NODES + 1];
__device__ int   g_bsum[64];
__device__ int   g_bflag[64];
__device__ float g_dinv[N_NODES];
__device__ int2  g_edge[N_EDGES];                // CSR: (src, wn-as-bits)
__device__ __half2 g_Whf[4 * 8192 + 1024];       // fp16 "big": W1,W2,W3,lw1,lw2
__device__ __half2 g_Wlf[4 * 8192 + 1024];       // fp16 residuals
__device__ __half2 g_y[(size_t)N_NODES * 64];    // GEMM output (fp16 messages)
__device__ __half2 g_h[(size_t)N_NODES * 64];    // activations (fp16)

// ---------------- init: counters + dtype detect + weight packs + x->fp16 ---
// grid 256 x 256 = 65536 threads
__global__ void k_init(const int* __restrict__ e,
                       const float* __restrict__ W1, const float* __restrict__ W2,
                       const float* __restrict__ W3, const float* __restrict__ lw1,
                       const float* __restrict__ lw2,
                       const float* __restrict__ x, const float* __restrict__ imp) {
    int idx = blockIdx.x * 256 + threadIdx.x;
    if (idx < N_NODES) g_cnt[idx] = 0;
    if (idx < 64) g_bflag[idx] = 0;

    if (idx < 32768) {                           // 4 mats x 8192 (k2,n) half2 packs
        int m = idx >> 13, r = idx & 8191;
        int k2 = r >> 7, n = r & 127;
        const float* src = (m == 0) ? W1 : (m == 1) ? W2 : (m == 2) ? W3 : lw1;
        float w0 = src[(2 * k2) * 128 + n];
        float w1 = src[(2 * k2 + 1) * 128 + n];
        __half h0 = __float2half_rn(w0), h1 = __float2half_rn(w1);
        g_Whf[idx] = __halves2half2(h0, h1);
        g_Wlf[idx] = __halves2half2(__float2half_rn(w0 - __half2float(h0)),
                                    __float2half_rn(w1 - __half2float(h1)));
    } else if (idx < 33792) {                    // lw2: 1024 (k2,n) packs
        int j = idx - 32768;
        int k2 = j >> 4, n = j & 15;
        float w0 = lw2[(2 * k2) * 16 + n];
        float w1 = lw2[(2 * k2 + 1) * 16 + n];
        __half h0 = __float2half_rn(w0), h1 = __float2half_rn(w1);
        g_Whf[32768 + j] = __halves2half2(h0, h1);
        g_Wlf[32768 + j] = __halves2half2(__float2half_rn(w0 - __half2float(h0)),
                                          __float2half_rn(w1 - __half2float(h1)));
    }

    // x * importance -> fp16 into g_h  (800000 uint4 = 50000 rows x 16 segs)
    for (int j = idx; j < N_NODES * 16; j += 65536) {
        int row = j >> 4, seg = j & 15;
        const float4* px = (const float4*)(x + (size_t)row * HDIM + seg * 8);
        float4 a = px[0], b = px[1];
        const float4* pi = (const float4*)(imp + seg * 8);
        float4 i0 = pi[0], i1 = pi[1];
        __half2 h0 = __floats2half2_rn(a.x * i0.x, a.y * i0.y);
        __half2 h1 = __floats2half2_rn(a.z * i0.z, a.w * i0.w);
        __half2 h2 = __floats2half2_rn(b.x * i1.x, b.y * i1.y);
        __half2 h3 = __floats2half2_rn(b.z * i1.z, b.w * i1.w);
        uint4 o;
        o.x = *(unsigned*)&h0; o.y = *(unsigned*)&h1;
        o.z = *(unsigned*)&h2; o.w = *(unsigned*)&h3;
        *(uint4*)(g_h + (size_t)row * 64 + seg * 4) = o;
    }

    if (blockIdx.x == 0) {
        __shared__ int any;
        if (threadIdx.x == 0) any = 0;
        __syncthreads();
        int w = e[2 * threadIdx.x + 1];   // odd words zero <=> int64 indices
        if (w != 0) atomicOr(&any, 1);
        __syncthreads();
        if (threadIdx.x == 0) g_is64 = (any == 0) ? 1 : 0;
    }
}

// histogram only (no rc store; fill re-reads the L2-hot edge tensor)
__global__ void k_hist(const void* __restrict__ edge) {
    int e = blockIdx.x * blockDim.x + threadIdx.x;
    if (e >= N_EDGES) return;
    int c;
    if (g_is64) c = (int)((const long long*)edge)[N_EDGES + e];
    else        c = ((const int*)edge)[N_EDGES + e];
    atomicAdd(&g_cnt[c], 1);
}

// single-pass exclusive scan with decoupled lookback (+ dinv fused)
__global__ void k_scan() {
    __shared__ int s[1024];
    __shared__ int pre;
    int idx = blockIdx.x * 1024 + threadIdx.x;
    int v = (idx < N_NODES) ? g_cnt[idx] : 0;
    if (idx < N_NODES) g_dinv[idx] = rsqrtf((float)(v + 1));
    s[threadIdx.x] = v;
    __syncthreads();
    for (int off = 1; off < 1024; off <<= 1) {
        int t = (threadIdx.x >= off) ? s[threadIdx.x - off] : 0;
        __syncthreads();
        s[threadIdx.x] += t;
        __syncthreads();
    }
    if (threadIdx.x == 1023) {
        g_bsum[blockIdx.x] = s[1023];
        __threadfence();
        atomicExch(&g_bflag[blockIdx.x], 1);
    }
    if (threadIdx.x < 32) {
        int p = 0;
        for (int i = threadIdx.x; i < blockIdx.x; i += 32) {
            while (atomicAdd(&g_bflag[i], 0) == 0) { __nanosleep(100); }
            p += atomicAdd(&g_bsum[i], 0);
        }
#pragma unroll
        for (int o = 16; o; o >>= 1) p += __shfl_xor_sync(0xffffffffu, p, o);
        if (threadIdx.x == 0) pre = p;
    }
    __syncthreads();
    if (idx < N_NODES) g_ptr[idx] = s[threadIdx.x] - v + pre;
    if (idx == 0) g_ptr[N_NODES] = N_EDGES;
}

// bucket fill: cursor = atomicSub on g_cnt; reads edges directly (L2-hot)
__global__ void k_fill(const void* __restrict__ edge) {
    int e = blockIdx.x * blockDim.x + threadIdx.x;
    if (e >= N_EDGES) return;
    int r, c;
    if (g_is64) {
        const long long* p = (const long long*)edge;
        r = (int)p[e];
        c = (int)p[N_EDGES + e];
    } else {
        const int* p = (const int*)edge;
        r = p[e];
        c = p[N_EDGES + e];
    }
    int pos = atomicSub(&g_cnt[c], 1) - 1;
    float w = g_dinv[r] * g_dinv[c];
    g_edge[g_ptr[c] + pos] = make_int2(r, __float_as_int(w));
}

// ---------------- mma / math helpers ---------------------------------------
__device__ __forceinline__ void mma_f16(float* d, const unsigned* a, const unsigned* b) {
    asm volatile(
        "mma.sync.aligned.m16n8k16.row.col.f32.f16.f16.f32 "
        "{%0,%1,%2,%3}, {%4,%5,%6,%7}, {%8,%9}, {%0,%1,%2,%3};"
        : "+f"(d[0]), "+f"(d[1]), "+f"(d[2]), "+f"(d[3])
        : "r"(a[0]), "r"(a[1]), "r"(a[2]), "r"(a[3]), "r"(b[0]), "r"(b[1]));
}

__device__ __forceinline__ float gelu_exact(float v) {
    return 0.5f * v * (1.f + erff(v * 0.70710678118654752f));
}

// ---------------- fp16 HMMA GEMM (FINAL=1 fuses head projection) ------------
// A fp16, W = Wh + Wl fp16 split, 2-term m16n8k16. 8 warps 2(M)x4(N).
#define AHS 20     // half2 stride of A smem row
#define WHS 136    // half2 stride of W smem k2-row
#define TSS 68     // half2 stride of fused-final T tile row
#define W2S 20     // half2 stride of lw2 smem k2-row

template <int FINAL>
__global__ void k_gemm_f16(const __half2* __restrict__ A,
                           const __half2* __restrict__ Wh_, const __half2* __restrict__ Wl_,
                           __half2* __restrict__ Y,
                           const float* __restrict__ lb1,
                           const __half2* __restrict__ W2h_, const __half2* __restrict__ W2l_,
                           const float* __restrict__ lb2, float* __restrict__ out) {
    extern __shared__ unsigned char smraw[];
    __half2* As  = (__half2*)smraw;                    // 128*AHS  (10240 B)
    __half2* Whs = (__half2*)(smraw + 10240);          // 16*WHS   (8704 B)
    __half2* Wls = (__half2*)(smraw + 18944);          // 16*WHS   (8704 B)

    int tid = threadIdx.x, lane = tid & 31, wid = tid >> 5;
    int wm = wid >> 2, wn = wid & 3;
    int g = lane >> 2, t4 = lane & 3;
    int row0 = blockIdx.x * 128;

    float acc[4][4][4];
#pragma unroll
    for (int mt = 0; mt < 4; mt++)
#pragma unroll
        for (int nt = 0; nt < 4; nt++)
#pragma unroll
            for (int r = 0; r < 4; r++) acc[mt][nt][r] = 0.f;

    int ar = tid >> 1, part = tid & 1;
    int wkr = tid >> 4, wnq = (tid & 15) * 8;

    for (int kt = 0; kt < 4; kt++) {
        uint4 au0 = make_uint4(0, 0, 0, 0), au1 = au0;
        {
            int gr = row0 + ar;
            if (gr < N_NODES) {
                const uint4* p = (const uint4*)(A + (size_t)gr * 64 + kt * 16 + part * 8);
                au0 = p[0]; au1 = p[1];
            }
        }
        const uint4* ph = (const uint4*)(Wh_ + (size_t)(kt * 16 + wkr) * 128 + wnq);
        const uint4* pl = (const uint4*)(Wl_ + (size_t)(kt * 16 + wkr) * 128 + wnq);
        uint4 wh0 = ph[0], wh1 = ph[1];
        uint4 wl0 = pl[0], wl1 = pl[1];

        __syncthreads();
        {
            uint4* q = (uint4*)(As + ar * AHS + part * 8);
            q[0] = au0; q[1] = au1;
            uint4* qh = (uint4*)(Whs + wkr * WHS + wnq);
            qh[0] = wh0; qh[1] = wh1;
            uint4* ql = (uint4*)(Wls + wkr * WHS + wnq);
            ql[0] = wl0; ql[1] = wl1;
        }
        __syncthreads();

#pragma unroll
        for (int ks = 0; ks < 2; ks++) {
            int kb = ks * 8;
            unsigned a[4][4];
#pragma unroll
            for (int mt = 0; mt < 4; mt++) {
                int rb = wm * 64 + mt * 16;
                a[mt][0] = *(unsigned*)&As[(rb + g) * AHS + kb + t4];
                a[mt][1] = *(unsigned*)&As[(rb + g + 8) * AHS + kb + t4];
                a[mt][2] = *(unsigned*)&As[(rb + g) * AHS + kb + t4 + 4];
                a[mt][3] = *(unsigned*)&As[(rb + g + 8) * AHS + kb + t4 + 4];
            }
            unsigned bh[4][2], bl[4][2];
#pragma unroll
            for (int nt = 0; nt < 4; nt++) {
                int n0 = wn * 32 + nt * 8;
                bh[nt][0] = *(unsigned*)&Whs[(kb + t4) * WHS + n0 + g];
                bh[nt][1] = *(unsigned*)&Whs[(kb + t4 + 4) * WHS + n0 + g];
                bl[nt][0] = *(unsigned*)&Wls[(kb + t4) * WHS + n0 + g];
                bl[nt][1] = *(unsigned*)&Wls[(kb + t4 + 4) * WHS + n0 + g];
            }
#pragma unroll
            for (int mt = 0; mt < 4; mt++)
#pragma unroll
                for (int nt = 0; nt < 4; nt++) {
                    mma_f16(acc[mt][nt], a[mt], bh[nt]);
                    mma_f16(acc[mt][nt], a[mt], bl[nt]);
                }
        }
    }

    if (FINAL == 0) {
#pragma unroll
        for (int mt = 0; mt < 4; mt++) {
            int r1 = row0 + wm * 64 + mt * 16 + g;
            int r2 = r1 + 8;
#pragma unroll
            for (int nt = 0; nt < 4; nt++) {
                int ch = wn * 16 + nt * 4 + t4;
                if (r1 < N_NODES)
                    Y[(size_t)r1 * 64 + ch] = __floats2half2_rn(acc[mt][nt][0], acc[mt][nt][1]);
                if (r2 < N_NODES)
                    Y[(size_t)r2 * 64 + ch] = __floats2half2_rn(acc[mt][nt][2], acc[mt][nt][3]);
            }
        }
    } else {
        // fused head: T = gelu(acc + lb1) in smem, then T @ lw2 (+lb2) -> out
        __half2* Ts   = (__half2*)smraw;                 // 128*TSS  (34816 B)
        __half2* W2hs = (__half2*)(smraw + 34816);       // 64*W2S   (5120 B)
        __half2* W2ls = (__half2*)(smraw + 39936);       // 64*W2S   (5120 B)
        __syncthreads();
        {
            int k2 = tid >> 2, n4 = (tid & 3) * 4;
            *(uint4*)(W2hs + k2 * W2S + n4) = ((const uint4*)W2h_)[tid];
            *(uint4*)(W2ls + k2 * W2S + n4) = ((const uint4*)W2l_)[tid];
        }
#pragma unroll
        for (int mt = 0; mt < 4; mt++) {
            int rl1 = wm * 64 + mt * 16 + g;
            int rl2 = rl1 + 8;
#pragma unroll
            for (int nt = 0; nt < 4; nt++) {
                int c = wn * 32 + nt * 8 + 2 * t4;
                int ch = c >> 1;
                float2 lb = *(const float2*)(lb1 + c);
                Ts[rl1 * TSS + ch] = __floats2half2_rn(gelu_exact(acc[mt][nt][0] + lb.x),
                                                       gelu_exact(acc[mt][nt][1] + lb.y));
                Ts[rl2 * TSS + ch] = __floats2half2_rn(gelu_exact(acc[mt][nt][2] + lb.x),
                                                       gelu_exact(acc[mt][nt][3] + lb.y));
            }
        }
        __syncthreads();
        int rb2 = wid * 16;
        float f2[2][4];
#pragma unroll
        for (int n2 = 0; n2 < 2; n2++)
#pragma unroll
            for (int r = 0; r < 4; r++) f2[n2][r] = 0.f;
#pragma unroll
        for (int kq = 0; kq < 8; kq++) {
            unsigned a[4];
            a[0] = *(unsigned*)&Ts[(rb2 + g) * TSS + kq * 8 + t4];
            a[1] = *(unsigned*)&Ts[(rb2 + g + 8) * TSS + kq * 8 + t4];
            a[2] = *(unsigned*)&Ts[(rb2 + g) * TSS + kq * 8 + t4 + 4];
            a[3] = *(unsigned*)&Ts[(rb2 + g + 8) * TSS + kq * 8 + t4 + 4];
#pragma unroll
            for (int n2 = 0; n2 < 2; n2++) {
                unsigned bh[2], bl[2];
                bh[0] = *(unsigned*)&W2hs[(kq * 8 + t4) * W2S + n2 * 8 + g];
                bh[1] = *(unsigned*)&W2hs[(kq * 8 + t4 + 4) * W2S + n2 * 8 + g];
                bl[0] = *(unsigned*)&W2ls[(kq * 8 + t4) * W2S + n2 * 8 + g];
                bl[1] = *(unsigned*)&W2ls[(kq * 8 + t4 + 4) * W2S + n2 * 8 + g];
                mma_f16(f2[n2], a, bh);
                mma_f16(f2[n2], a, bl);
            }
        }
        int r1 = row0 + rb2 + g, r2 = r1 + 8;
#pragma unroll
        for (int n2 = 0; n2 < 2; n2++) {
            int c = n2 * 8 + 2 * t4;
            float2 lb = *(const float2*)(lb2 + c);
            if (r1 < N_NODES)
                *(float2*)(out + (size_t)r1 * CDIM + c) = make_float2(f2[n2][0] + lb.x, f2[n2][1] + lb.y);
            if (r2 < N_NODES)
                *(float2*)(out + (size_t)r2 * CDIM + c) = make_float2(f2[n2][2] + lb.x, f2[n2][3] + lb.y);
        }
    }
}

// ---------------- aggregation (shfl-free, 16 lanes/node, packed edges) ------
__device__ __forceinline__ void fma8(float* acc, uint4 u, float w) {
    float2 a = __half22float2(*(__half2*)&u.x);
    float2 b = __half22float2(*(__half2*)&u.y);
    float2 c = __half22float2(*(__half2*)&u.z);
    float2 d = __half22float2(*(__half2*)&u.w);
    acc[0] += w * a.x; acc[1] += w * a.y;
    acc[2] += w * b.x; acc[3] += w * b.y;
    acc[4] += w * c.x; acc[5] += w * c.y;
    acc[6] += w * d.x; acc[7] += w * d.y;
}

__global__ void k_agg(const __half2* __restrict__ Y, const float* __restrict__ b,
                      __half2* __restrict__ H) {
    int tid  = threadIdx.x;
    int warp = tid >> 5;
    int lane = tid & 31;
    int sub  = lane & 15;
    int c = blockIdx.x * 16 + warp * 2 + (lane >> 4);

    float dc = g_dinv[c];
    float sw = dc * dc;
    float acc[8] = {0, 0, 0, 0, 0, 0, 0, 0};
    fma8(acc, *(const uint4*)(Y + (size_t)c * 64 + sub * 4), sw);

    int beg = g_ptr[c], end = g_ptr[c + 1];
    int i = beg;
    for (; i + 4 <= end; i += 4) {
        int2 e0 = g_edge[i],     e1 = g_edge[i + 1];
        int2 e2 = g_edge[i + 2], e3 = g_edge[i + 3];
        uint4 u0 = *(const uint4*)(Y + (size_t)e0.x * 64 + sub * 4);
        uint4 u1 = *(const uint4*)(Y + (size_t)e1.x * 64 + sub * 4);
        uint4 u2 = *(const uint4*)(Y + (size_t)e2.x * 64 + sub * 4);
        uint4 u3 = *(const uint4*)(Y + (size_t)e3.x * 64 + sub * 4);
        fma8(acc, u0, __int_as_float(e0.y));
        fma8(acc, u1, __int_as_float(e1.y));
        fma8(acc, u2, __int_as_float(e2.y));
        fma8(acc, u3, __int_as_float(e3.y));
    }
    for (; i < end; i++) {
        int2 e = g_edge[i];
        fma8(acc, *(const uint4*)(Y + (size_t)e.x * 64 + sub * 4), __int_as_float(e.y));
    }

    const float4 b0 = *(const float4*)(b + sub * 8);
    const float4 b1 = *(const float4*)(b + sub * 8 + 4);
    uint4 o;
    __half2 h0 = __floats2half2_rn(gelu_exact(acc[0] + b0.x), gelu_exact(acc[1] + b0.y));
    __half2 h1 = __floats2half2_rn(gelu_exact(acc[2] + b0.z), gelu_exact(acc[3] + b0.w));
    __half2 h2 = __floats2half2_rn(gelu_exact(acc[4] + b1.x), gelu_exact(acc[5] + b1.y));
    __half2 h3 = __floats2half2_rn(gelu_exact(acc[6] + b1.z), gelu_exact(acc[7] + b1.w));
    o.x = *(unsigned*)&h0; o.y = *(unsigned*)&h1; o.z = *(unsigned*)&h2; o.w = *(unsigned*)&h3;
    *(uint4*)(H + (size_t)c * 64 + sub * 4) = o;
}

// ---------------- launch ---------------------------------------------------
extern "C" void kernel_launch(void* const* d_in, const int* in_sizes, int n_in,
                              void* d_out, int out_size) {
    const float* x    = (const float*)d_in[0];
    const void*  edge = d_in[1];
    const float* imp  = (const float*)d_in[2];
    const float* W1   = (const float*)d_in[3];
    const float* b1   = (const float*)d_in[4];
    const float* W2   = (const float*)d_in[5];
    const float* b2   = (const float*)d_in[6];
    const float* W3   = (const float*)d_in[7];
    const float* b3   = (const float*)d_in[8];
    const float* lw1  = (const float*)d_in[9];
    const float* lb1  = (const float*)d_in[10];
    const float* lw2  = (const float*)d_in[11];
    const float* lb2  = (const float*)d_in[12];
    float* out = (float*)d_out;

    const int EB = (N_EDGES + 255) / 256;      // 3125
    const int SB = (N_NODES + 1023) / 1024;    // 49
    const int GB = (N_NODES + 127) / 128;      // 391
    const int AB = N_NODES / 16;               // 3125

    __half2* y; cudaGetSymbolAddress((void**)&y, g_y);
    __half2* h; cudaGetSymbolAddress((void**)&h, g_h);
    __half2* wh; cudaGetSymbolAddress((void**)&wh, g_Whf);
    __half2* wl; cudaGetSymbolAddress((void**)&wl, g_Wlf);

    const int SM_MAIN = 27648;   // As + Wh + Wl
    const int SM_FIN  = 45056;   // Ts + W2h + W2l overlay

    // --- init (counters, weight packs, x->fp16, dtype) + CSR build ---
    k_init<<<256, 256>>>((const int*)edge, W1, W2, W3, lw1, lw2, x, imp);
    k_hist<<<EB, 256>>>(edge);
    k_scan<<<SB, 1024>>>();
    k_fill<<<EB, 256>>>(edge);

    // --- layer 1 (fp16 A = x*imp, 2-term) ---
    k_gemm_f16<0><<<GB, 256, SM_MAIN>>>(h, wh, wl, y, nullptr, nullptr, nullptr, nullptr, nullptr);
    k_agg<<<AB, 256>>>(y, b1, h);
    // --- layer 2 ---
    k_gemm_f16<0><<<GB, 256, SM_MAIN>>>(h, wh + 8192, wl + 8192, y, nullptr, nullptr, nullptr, nullptr, nullptr);
    k_agg<<<AB, 256>>>(y, b2, h);
    // --- layer 3 ---
    k_gemm_f16<0><<<GB, 256, SM_MAIN>>>(h, wh + 16384, wl + 16384, y, nullptr, nullptr, nullptr, nullptr, nullptr);
    k_agg<<<AB, 256>>>(y, b3, h);
    // --- head (fused: gelu(h@lw1+lb1) @ lw2 + lb2 -> out) ---
    k_gemm_f16<1><<<GB, 256, SM_FIN>>>(h, wh + 24576, wl + 24576, nullptr, lb1,
                                       wh + 32768, wl + 32768, lb2, out);
}

// round 16
// speedup vs baseline: 1.3944x; 1.0010x over previous
#include <cuda_runtime.h>
#include <cuda_fp16.h>
#include <math.h>

#define N_NODES 50000
#define N_EDGES 800000
#define HDIM 128
#define CDIM 16

// ---------------- scratch (device globals; no allocation) ----------------
// INVARIANT: g_cnt is all-zero at every kernel_launch entry (zero-init at
// module load; k_fill's atomicSub drains it back to zero each launch).
__device__ int   g_is64;
__device__ int   g_cnt[N_NODES];
__device__ int   g_ptr[N_NODES + 1];
__device__ int   g_bsum[64];
__device__ int   g_bflag[64];
__device__ float g_dinv[N_NODES];
__device__ int   g_src[N_EDGES];                 // CSR: source node per slot
__device__ __half2 g_Whf[4 * 8192 + 1024];       // fp16 "big": W1,W2,W3,lw1,lw2
__device__ __half2 g_Wlf[4 * 8192 + 1024];       // fp16 residuals
__device__ __half2 g_y[(size_t)N_NODES * 64];    // GEMM output (fp16 messages)
__device__ __half2 g_h[(size_t)N_NODES * 64];    // activations (fp16)

// ---------------- init + histogram (merged; cnt-zeroing eliminated) --------
// grid 256 x 256 = 65536 threads. Each block locally re-derives the edge
// dtype from the first 256 edges (deterministic, identical across blocks).
__global__ void k_inithist(const int* __restrict__ e,
                           const float* __restrict__ W1, const float* __restrict__ W2,
                           const float* __restrict__ W3, const float* __restrict__ lw1,
                           const float* __restrict__ lw2,
                           const float* __restrict__ x, const float* __restrict__ imp) {
    __shared__ int any;
    int tid = threadIdx.x;
    if (tid == 0) any = 0;
    __syncthreads();
    if (e[2 * tid + 1] != 0) atomicOr(&any, 1);   // odd words zero <=> int64
    __syncthreads();
    int is64 = (any == 0);

    int idx = blockIdx.x * 256 + tid;
    if (idx == 0) g_is64 = is64;
    if (idx < 64) g_bflag[idx] = 0;

    if (idx < 32768) {                           // 4 mats x 8192 (k2,n) half2 packs
        int m = idx >> 13, r = idx & 8191;
        int k2 = r >> 7, n = r & 127;
        const float* src = (m == 0) ? W1 : (m == 1) ? W2 : (m == 2) ? W3 : lw1;
        float w0 = src[(2 * k2) * 128 + n];
        float w1 = src[(2 * k2 + 1) * 128 + n];
        __half h0 = __float2half_rn(w0), h1 = __float2half_rn(w1);
        g_Whf[idx] = __halves2half2(h0, h1);
        g_Wlf[idx] = __halves2half2(__float2half_rn(w0 - __half2float(h0)),
                                    __float2half_rn(w1 - __half2float(h1)));
    } else if (idx < 33792) {                    // lw2: 1024 (k2,n) packs
        int j = idx - 32768;
        int k2 = j >> 4, n = j & 15;
        float w0 = lw2[(2 * k2) * 16 + n];
        float w1 = lw2[(2 * k2 + 1) * 16 + n];
        __half h0 = __float2half_rn(w0), h1 = __float2half_rn(w1);
        g_Whf[32768 + j] = __halves2half2(h0, h1);
        g_Wlf[32768 + j] = __halves2half2(__float2half_rn(w0 - __half2float(h0)),
                                          __float2half_rn(w1 - __half2float(h1)));
    }

    // x * importance -> fp16 into g_h
    for (int j = idx; j < N_NODES * 16; j += 65536) {
        int row = j >> 4, seg = j & 15;
        const float4* px = (const float4*)(x + (size_t)row * HDIM + seg * 8);
        float4 a = px[0], b = px[1];
        const float4* pi = (const float4*)(imp + seg * 8);
        float4 i0 = pi[0], i1 = pi[1];
        __half2 h0 = __floats2half2_rn(a.x * i0.x, a.y * i0.y);
        __half2 h1 = __floats2half2_rn(a.z * i0.z, a.w * i0.w);
        __half2 h2 = __floats2half2_rn(b.x * i1.x, b.y * i1.y);
        __half2 h3 = __floats2half2_rn(b.z * i1.z, b.w * i1.w);
        uint4 o;
        o.x = *(unsigned*)&h0; o.y = *(unsigned*)&h1;
        o.z = *(unsigned*)&h2; o.w = *(unsigned*)&h3;
        *(uint4*)(g_h + (size_t)row * 64 + seg * 4) = o;
    }

    // histogram (grid-strided; relies on cnt==0 invariant)
    if (is64) {
        const long long* p = (const long long*)e;
        for (int j = idx; j < N_EDGES; j += 65536)
            atomicAdd(&g_cnt[(int)p[N_EDGES + j]], 1);
    } else {
        for (int j = idx; j < N_EDGES; j += 65536)
            atomicAdd(&g_cnt[e[N_EDGES + j]], 1);
    }
}

// single-pass exclusive scan with decoupled lookback (+ dinv fused)
__global__ void k_scan() {
    __shared__ int s[1024];
    __shared__ int pre;
    int idx = blockIdx.x * 1024 + threadIdx.x;
    int v = (idx < N_NODES) ? g_cnt[idx] : 0;
    if (idx < N_NODES) g_dinv[idx] = rsqrtf((float)(v + 1));
    s[threadIdx.x] = v;
    __syncthreads();
    for (int off = 1; off < 1024; off <<= 1) {
        int t = (threadIdx.x >= off) ? s[threadIdx.x - off] : 0;
        __syncthreads();
        s[threadIdx.x] += t;
        __syncthreads();
    }
    if (threadIdx.x == 1023) {
        g_bsum[blockIdx.x] = s[1023];
        __threadfence();
        atomicExch(&g_bflag[blockIdx.x], 1);
    }
    if (threadIdx.x < 32) {
        int p = 0;
        for (int i = threadIdx.x; i < blockIdx.x; i += 32) {
            while (atomicAdd(&g_bflag[i], 0) == 0) { __nanosleep(100); }
            p += atomicAdd(&g_bsum[i], 0);
        }
#pragma unroll
        for (int o = 16; o; o >>= 1) p += __shfl_xor_sync(0xffffffffu, p, o);
        if (threadIdx.x == 0) pre = p;
    }
    __syncthreads();
    if (idx < N_NODES) g_ptr[idx] = s[threadIdx.x] - v + pre;
    if (idx == 0) g_ptr[N_NODES] = N_EDGES;
}

// bucket fill: cursor = atomicSub on g_cnt (drains it to 0); 4B src-only store
__global__ void k_fill(const void* __restrict__ edge) {
    int e = blockIdx.x * blockDim.x + threadIdx.x;
    if (e >= N_EDGES) return;
    int r, c;
    if (g_is64) {
        const long long* p = (const long long*)edge;
        r = (int)p[e];
        c = (int)p[N_EDGES + e];
    } else {
        const int* p = (const int*)edge;
        r = p[e];
        c = p[N_EDGES + e];
    }
    int pos = atomicSub(&g_cnt[c], 1) - 1;
    g_src[g_ptr[c] + pos] = r;
}

// ---------------- mma / math helpers ---------------------------------------
__device__ __forceinline__ void mma_f16(float* d, const unsigned* a, const unsigned* b) {
    asm volatile(
        "mma.sync.aligned.m16n8k16.row.col.f32.f16.f16.f32 "
        "{%0,%1,%2,%3}, {%4,%5,%6,%7}, {%8,%9}, {%0,%1,%2,%3};"
        : "+f"(d[0]), "+f"(d[1]), "+f"(d[2]), "+f"(d[3])
        : "r"(a[0]), "r"(a[1]), "r"(a[2]), "r"(a[3]), "r"(b[0]), "r"(b[1]));
}

__device__ __forceinline__ float gelu_exact(float v) {
    return 0.5f * v * (1.f + erff(v * 0.70710678118654752f));
}

// ---------------- fp16 HMMA GEMM (FINAL=1 fuses head projection) ------------
#define AHS 20     // half2 stride of A smem row
#define WHS 136    // half2 stride of W smem k2-row
#define TSS 68     // half2 stride of fused-final T tile row
#define W2S 20     // half2 stride of lw2 smem k2-row

template <int FINAL>
__global__ void k_gemm_f16(const __half2* __restrict__ A,
                           const __half2* __restrict__ Wh_, const __half2* __restrict__ Wl_,
                           __half2* __restrict__ Y,
                           const float* __restrict__ lb1,
                           const __half2* __restrict__ W2h_, const __half2* __restrict__ W2l_,
                           const float* __restrict__ lb2, float* __restrict__ out) {
    extern __shared__ unsigned char smraw[];
    __half2* As  = (__half2*)smraw;                    // 128*AHS  (10240 B)
    __half2* Whs = (__half2*)(smraw + 10240);          // 16*WHS   (8704 B)
    __half2* Wls = (__half2*)(smraw + 18944);          // 16*WHS   (8704 B)

    int tid = threadIdx.x, lane = tid & 31, wid = tid >> 5;
    int wm = wid >> 2, wn = wid & 3;
    int g = lane >> 2, t4 = lane & 3;
    int row0 = blockIdx.x * 128;

    float acc[4][4][4];
#pragma unroll
    for (int mt = 0; mt < 4; mt++)
#pragma unroll
        for (int nt = 0; nt < 4; nt++)
#pragma unroll
            for (int r = 0; r < 4; r++) acc[mt][nt][r] = 0.f;

    int ar = tid >> 1, part = tid & 1;
    int wkr = tid >> 4, wnq = (tid & 15) * 8;

    for (int kt = 0; kt < 4; kt++) {
        uint4 au0 = make_uint4(0, 0, 0, 0), au1 = au0;
        {
            int gr = row0 + ar;
            if (gr < N_NODES) {
                const uint4* p = (const uint4*)(A + (size_t)gr * 64 + kt * 16 + part * 8);
                au0 = p[0]; au1 = p[1];
            }
        }
        const uint4* ph = (const uint4*)(Wh_ + (size_t)(kt * 16 + wkr) * 128 + wnq);
        const uint4* pl = (const uint4*)(Wl_ + (size_t)(kt * 16 + wkr) * 128 + wnq);
        uint4 wh0 = ph[0], wh1 = ph[1];
        uint4 wl0 = pl[0], wl1 = pl[1];

        __syncthreads();
        {
            uint4* q = (uint4*)(As + ar * AHS + part * 8);
            q[0] = au0; q[1] = au1;
            uint4* qh = (uint4*)(Whs + wkr * WHS + wnq);
            qh[0] = wh0; qh[1] = wh1;
            uint4* ql = (uint4*)(Wls + wkr * WHS + wnq);
            ql[0] = wl0; ql[1] = wl1;
        }
        __syncthreads();

#pragma unroll
        for (int ks = 0; ks < 2; ks++) {
            int kb = ks * 8;
            unsigned a[4][4];
#pragma unroll
            for (int mt = 0; mt < 4; mt++) {
                int rb = wm * 64 + mt * 16;
                a[mt][0] = *(unsigned*)&As[(rb + g) * AHS + kb + t4];
                a[mt][1] = *(unsigned*)&As[(rb + g + 8) * AHS + kb + t4];
                a[mt][2] = *(unsigned*)&As[(rb + g) * AHS + kb + t4 + 4];
                a[mt][3] = *(unsigned*)&As[(rb + g + 8) * AHS + kb + t4 + 4];
            }
            unsigned bh[4][2], bl[4][2];
#pragma unroll
            for (int nt = 0; nt < 4; nt++) {
                int n0 = wn * 32 + nt * 8;
                bh[nt][0] = *(unsigned*)&Whs[(kb + t4) * WHS + n0 + g];
                bh[nt][1] = *(unsigned*)&Whs[(kb + t4 + 4) * WHS + n0 + g];
                bl[nt][0] = *(unsigned*)&Wls[(kb + t4) * WHS + n0 + g];
                bl[nt][1] = *(unsigned*)&Wls[(kb + t4 + 4) * WHS + n0 + g];
            }
#pragma unroll
            for (int mt = 0; mt < 4; mt++)
#pragma unroll
                for (int nt = 0; nt < 4; nt++) {
                    mma_f16(acc[mt][nt], a[mt], bh[nt]);
                    mma_f16(acc[mt][nt], a[mt], bl[nt]);
                }
        }
    }

    if (FINAL == 0) {
#pragma unroll
        for (int mt = 0; mt < 4; mt++) {
            int r1 = row0 + wm * 64 + mt * 16 + g;
            int r2 = r1 + 8;
#pragma unroll
            for (int nt = 0; nt < 4; nt++) {
                int ch = wn * 16 + nt * 4 + t4;
                if (r1 < N_NODES)
                    Y[(size_t)r1 * 64 + ch] = __floats2half2_rn(acc[mt][nt][0], acc[mt][nt][1]);
                if (r2 < N_NODES)
                    Y[(size_t)r2 * 64 + ch] = __floats2half2_rn(acc[mt][nt][2], acc[mt][nt][3]);
            }
        }
    } else {
        // fused head: T = gelu(acc + lb1) in smem, then T @ lw2 (+lb2) -> out
        __half2* Ts   = (__half2*)smraw;                 // 128*TSS  (34816 B)
        __half2* W2hs = (__half2*)(smraw + 34816);       // 64*W2S   (5120 B)
        __half2* W2ls = (__half2*)(smraw + 39936);       // 64*W2S   (5120 B)
        __syncthreads();
        {
            int k2 = tid >> 2, n4 = (tid & 3) * 4;
            *(uint4*)(W2hs + k2 * W2S + n4) = ((const uint4*)W2h_)[tid];
            *(uint4*)(W2ls + k2 * W2S + n4) = ((const uint4*)W2l_)[tid];
        }
#pragma unroll
        for (int mt = 0; mt < 4; mt++) {
            int rl1 = wm * 64 + mt * 16 + g;
            int rl2 = rl1 + 8;
#pragma unroll
            for (int nt = 0; nt < 4; nt++) {
                int c = wn * 32 + nt * 8 + 2 * t4;
                int ch = c >> 1;
                float2 lb = *(const float2*)(lb1 + c);
                Ts[rl1 * TSS + ch] = __floats2half2_rn(gelu_exact(acc[mt][nt][0] + lb.x),
                                                       gelu_exact(acc[mt][nt][1] + lb.y));
                Ts[rl2 * TSS + ch] = __floats2half2_rn(gelu_exact(acc[mt][nt][2] + lb.x),
                                                       gelu_exact(acc[mt][nt][3] + lb.y));
            }
        }
        __syncthreads();
        int rb2 = wid * 16;
        float f2[2][4];
#pragma unroll
        for (int n2 = 0; n2 < 2; n2++)
#pragma unroll
            for (int r = 0; r < 4; r++) f2[n2][r] = 0.f;
#pragma unroll
        for (int kq = 0; kq < 8; kq++) {
            unsigned a[4];
            a[0] = *(unsigned*)&Ts[(rb2 + g) * TSS + kq * 8 + t4];
            a[1] = *(unsigned*)&Ts[(rb2 + g + 8) * TSS + kq * 8 + t4];
            a[2] = *(unsigned*)&Ts[(rb2 + g) * TSS + kq * 8 + t4 + 4];
            a[3] = *(unsigned*)&Ts[(rb2 + g + 8) * TSS + kq * 8 + t4 + 4];
#pragma unroll
            for (int n2 = 0; n2 < 2; n2++) {
                unsigned bh[2], bl[2];
                bh[0] = *(unsigned*)&W2hs[(kq * 8 + t4) * W2S + n2 * 8 + g];
                bh[1] = *(unsigned*)&W2hs[(kq * 8 + t4 + 4) * W2S + n2 * 8 + g];
                bl[0] = *(unsigned*)&W2ls[(kq * 8 + t4) * W2S + n2 * 8 + g];
                bl[1] = *(unsigned*)&W2ls[(kq * 8 + t4 + 4) * W2S + n2 * 8 + g];
                mma_f16(f2[n2], a, bh);
                mma_f16(f2[n2], a, bl);
            }
        }
        int r1 = row0 + rb2 + g, r2 = r1 + 8;
#pragma unroll
        for (int n2 = 0; n2 < 2; n2++) {
            int c = n2 * 8 + 2 * t4;
            float2 lb = *(const float2*)(lb2 + c);
            if (r1 < N_NODES)
                *(float2*)(out + (size_t)r1 * CDIM + c) = make_float2(f2[n2][0] + lb.x, f2[n2][1] + lb.y);
            if (r2 < N_NODES)
                *(float2*)(out + (size_t)r2 * CDIM + c) = make_float2(f2[n2][2] + lb.x, f2[n2][3] + lb.y);
        }
    }
}

// ---------------- aggregation (16 lanes/node; w recomputed from dinv) -------
__device__ __forceinline__ void fma8(float* acc, uint4 u, float w) {
    float2 a = __half22float2(*(__half2*)&u.x);
    float2 b = __half22float2(*(__half2*)&u.y);
    float2 c = __half22float2(*(__half2*)&u.z);
    float2 d = __half22float2(*(__half2*)&u.w);
    acc[0] += w * a.x; acc[1] += w * a.y;
    acc[2] += w * b.x; acc[3] += w * b.y;
    acc[4] += w * c.x; acc[5] += w * c.y;
    acc[6] += w * d.x; acc[7] += w * d.y;
}

__global__ void k_agg(const __half2* __restrict__ Y, const float* __restrict__ b,
                      __half2* __restrict__ H) {
    int tid  = threadIdx.x;
    int warp = tid >> 5;
    int lane = tid & 31;
    int sub  = lane & 15;
    int c = blockIdx.x * 16 + warp * 2 + (lane >> 4);

    float dc = g_dinv[c];
    float acc[8] = {0, 0, 0, 0, 0, 0, 0, 0};
    fma8(acc, *(const uint4*)(Y + (size_t)c * 64 + sub * 4), dc * dc);

    int beg = g_ptr[c], end = g_ptr[c + 1];
    int i = beg;
    for (; i + 4 <= end; i += 4) {
        int s0 = g_src[i],     s1 = g_src[i + 1];
        int s2 = g_src[i + 2], s3 = g_src[i + 3];
        float w0 = dc * g_dinv[s0], w1 = dc * g_dinv[s1];
        float w2 = dc * g_dinv[s2], w3 = dc * g_dinv[s3];
        uint4 u0 = *(const uint4*)(Y + (size_t)s0 * 64 + sub * 4);
        uint4 u1 = *(const uint4*)(Y + (size_t)s1 * 64 + sub * 4);
        uint4 u2 = *(const uint4*)(Y + (size_t)s2 * 64 + sub * 4);
        uint4 u3 = *(const uint4*)(Y + (size_t)s3 * 64 + sub * 4);
        fma8(acc, u0, w0); fma8(acc, u1, w1); fma8(acc, u2, w2); fma8(acc, u3, w3);
    }
    for (; i < end; i++) {
        int s = g_src[i];
        float w = dc * g_dinv[s];
        fma8(acc, *(const uint4*)(Y + (size_t)s * 64 + sub * 4), w);
    }

    const float4 b0 = *(const float4*)(b + sub * 8);
    const float4 b1 = *(const float4*)(b + sub * 8 + 4);
    uint4 o;
    __half2 h0 = __floats2half2_rn(gelu_exact(acc[0] + b0.x), gelu_exact(acc[1] + b0.y));
    __half2 h1 = __floats2half2_rn(gelu_exact(acc[2] + b0.z), gelu_exact(acc[3] + b0.w));
    __half2 h2 = __floats2half2_rn(gelu_exact(acc[4] + b1.x), gelu_exact(acc[5] + b1.y));
    __half2 h3 = __floats2half2_rn(gelu_exact(acc[6] + b1.z), gelu_exact(acc[7] + b1.w));
    o.x = *(unsigned*)&h0; o.y = *(unsigned*)&h1; o.z = *(unsigned*)&h2; o.w = *(unsigned*)&h3;
    *(uint4*)(H + (size_t)c * 64 + sub * 4) = o;
}

// ---------------- launch ---------------------------------------------------
extern "C" void kernel_launch(void* const* d_in, const int* in_sizes, int n_in,
                              void* d_out, int out_size) {
    const float* x    = (const float*)d_in[0];
    const void*  edge = d_in[1];
    const float* imp  = (const float*)d_in[2];
    const float* W1   = (const float*)d_in[3];
    const float* b1   = (const float*)d_in[4];
    const float* W2   = (const float*)d_in[5];
    const float* b2   = (const float*)d_in[6];
    const float* W3   = (const float*)d_in[7];
    const float* b3   = (const float*)d_in[8];
    const float* lw1  = (const float*)d_in[9];
    const float* lb1  = (const float*)d_in[10];
    const float* lw2  = (const float*)d_in[11];
    const float* lb2  = (const float*)d_in[12];
    float* out = (float*)d_out;

    const int EB = (N_EDGES + 255) / 256;      // 3125
    const int SB = (N_NODES + 1023) / 1024;    // 49
    const int GB = (N_NODES + 127) / 128;      // 391
    const int AB = N_NODES / 16;               // 3125

    __half2* y; cudaGetSymbolAddress((void**)&y, g_y);
    __half2* h; cudaGetSymbolAddress((void**)&h, g_h);
    __half2* wh; cudaGetSymbolAddress((void**)&wh, g_Whf);
    __half2* wl; cudaGetSymbolAddress((void**)&wl, g_Wlf);

    const int SM_MAIN = 27648;   // As + Wh + Wl
    const int SM_FIN  = 45056;   // Ts + W2h + W2l overlay

    // --- CSR build + weight packs + x->fp16 ---
    k_inithist<<<256, 256>>>((const int*)edge, W1, W2, W3, lw1, lw2, x, imp);
    k_scan<<<SB, 1024>>>();
    k_fill<<<EB, 256>>>(edge);

    // --- layer 1 (fp16 A = x*imp, 2-term) ---
    k_gemm_f16<0><<<GB, 256, SM_MAIN>>>(h, wh, wl, y, nullptr, nullptr, nullptr, nullptr, nullptr);
    k_agg<<<AB, 256>>>(y, b1, h);
    // --- layer 2 ---
    k_gemm_f16<0><<<GB, 256, SM_MAIN>>>(h, wh + 8192, wl + 8192, y, nullptr, nullptr, nullptr, nullptr, nullptr);
    k_agg<<<AB, 256>>>(y, b2, h);
    // --- layer 3 ---
    k_gemm_f16<0><<<GB, 256, SM_MAIN>>>(h, wh + 16384, wl + 16384, y, nullptr, nullptr, nullptr, nullptr, nullptr);
    k_agg<<<AB, 256>>>(y, b3, h);
    // --- head (fused: gelu(h@lw1+lb1) @ lw2 + lb2 -> out) ---
    k_gemm_f16<1><<<GB, 256, SM_FIN>>>(h, wh + 24576, wl + 24576, nullptr, lb1,
                                       wh + 32768, wl + 32768, lb2, out);
}